// round 16
// baseline (speedup 1.0000x reference)
#include <cuda_runtime.h>
#include <cuda_fp16.h>
#include <math.h>
#include <stdint.h>

// Problem constants
#define T_SEQ 128
#define B_SZ  32
#define H_SZ  512
#define V_SZ  32000
#define G3    1536          // 3*H
#define M_ROWS 4096         // B*T

// Scratch (device globals: allocation-free rule)
__device__ __align__(16) float g_xg[(size_t)M_ROWS * G3];          // [m=b*T+t][3H]
__device__ __align__(16) float g_hs[(size_t)T_SEQ * B_SZ * H_SZ];  // [t][b][h]
__device__ __align__(16) __half g_ah[(size_t)M_ROWS * H_SZ];       // A fp16 [m][512]
__device__ __align__(16) __half g_bh[(size_t)V_SZ * H_SZ];         // emb fp16 [v][512]
__device__ __align__(16) __half g_wh[(size_t)G3 * H_SZ];           // w_ih fp16 [g][512]
#define NBAR 8
#define BARSTRIDE 64
__device__ unsigned g_bars[NBAR * BARSTRIDE];
__device__ unsigned g_job;     // logits tile job counter
__device__ unsigned g_tdone;   // GRU progress (steps complete), release-published

// ---------- packed fp32x2 helpers ----------
static __device__ __forceinline__ unsigned long long f2fma(unsigned long long a,
                                                           unsigned long long b,
                                                           unsigned long long c) {
    unsigned long long d;
    asm("fma.rn.f32x2 %0, %1, %2, %3;" : "=l"(d) : "l"(a), "l"(b), "l"(c));
    return d;
}
static __device__ __forceinline__ float2 upk2(unsigned long long v) {
    float2 r;
    asm("mov.b64 {%0, %1}, %2;" : "=f"(r.x), "=f"(r.y) : "l"(v));
    return r;
}
static __device__ __forceinline__ float sigmoidf_(float x) {
    return 1.0f / (1.0f + expf(-x));
}
static __device__ __forceinline__ unsigned ld_acq(const unsigned* p) {
    unsigned v;
    asm volatile("ld.global.acquire.gpu.u32 %0, [%1];" : "=r"(v) : "l"(p) : "memory");
    return v;
}
static __device__ __forceinline__ void st_rel(unsigned* p, unsigned v) {
    asm volatile("st.global.release.gpu.u32 [%0], %1;" :: "l"(p), "r"(v) : "memory");
}
static __device__ __forceinline__ void nsleep(unsigned ns) {
    asm volatile("nanosleep.u32 %0;" :: "r"(ns));
}

// ---------- smem / async-copy / mma helpers (baseline PTX only) ----------
static __device__ __forceinline__ uint32_t smem_u32(const void* p) {
    uint32_t a;
    asm("{ .reg .u64 t; cvta.to.shared.u64 t, %1; cvt.u32.u64 %0, t; }"
        : "=r"(a) : "l"(p));
    return a;
}
static __device__ __forceinline__ void cp_async16(uint32_t dst, const void* src) {
    asm volatile("cp.async.cg.shared.global [%0], [%1], 16;" :: "r"(dst), "l"(src));
}
static __device__ __forceinline__ void cp_commit() {
    asm volatile("cp.async.commit_group;");
}
static __device__ __forceinline__ void cp_wait1() {
    asm volatile("cp.async.wait_group 1;" ::: "memory");
}
static __device__ __forceinline__ void ldsm4(uint32_t* r, uint32_t addr) {
    asm volatile("ldmatrix.sync.aligned.m8n8.x4.shared.b16 {%0,%1,%2,%3}, [%4];"
                 : "=r"(r[0]), "=r"(r[1]), "=r"(r[2]), "=r"(r[3]) : "r"(addr));
}
static __device__ __forceinline__ void mma16816h(float* c, const uint32_t* a,
                                                 uint32_t b0, uint32_t b1) {
    asm volatile(
        "mma.sync.aligned.m16n8k16.row.col.f32.f16.f16.f32 "
        "{%0,%1,%2,%3}, {%4,%5,%6,%7}, {%8,%9}, {%0,%1,%2,%3};"
        : "+f"(c[0]), "+f"(c[1]), "+f"(c[2]), "+f"(c[3])
        : "r"(a[0]), "r"(a[1]), "r"(a[2]), "r"(a[3]), "r"(b0), "r"(b1));
}

// 128B rows, seg 0..7 (16B units), classic SW128: seg' = seg ^ (row&7).
static __device__ __forceinline__ uint32_t swoff(int row, int seg) {
    return (uint32_t)((row << 7) + (((seg ^ row) & 7) << 4));
}

// =====================================================================
// Kernel 1: convert — emb fp32->fp16 (g_bh) and w_ih fp32->fp16 (g_wh)
// =====================================================================
union HF4 { __half h[4]; uint2 u; };

#define EMB_CONV_SLOTS (V_SZ * (H_SZ / 4))
#define WIH_CONV_SLOTS (G3 * (H_SZ / 4))
#define CONV_TOTAL (EMB_CONV_SLOTS + WIH_CONV_SLOTS)
#define CONV_GRID ((CONV_TOTAL + 255) / 256)

__global__ __launch_bounds__(256)
void convert_kernel(const float* __restrict__ emb,
                    const float* __restrict__ w_ih)
{
    int s = blockIdx.x * 256 + threadIdx.x;
    const float* src;
    __half* dst;
    if (s < EMB_CONV_SLOTS) {
        src = emb + (size_t)s * 4;
        dst = g_bh + (size_t)s * 4;
    } else {
        int s2 = s - EMB_CONV_SLOTS;
        if (s2 >= WIH_CONV_SLOTS) return;
        src = w_ih + (size_t)s2 * 4;
        dst = g_wh + (size_t)s2 * 4;
    }
    float4 x = *(const float4*)src;
    HF4 o;
    o.h[0] = __float2half_rn(x.x);
    o.h[1] = __float2half_rn(x.y);
    o.h[2] = __float2half_rn(x.z);
    o.h[3] = __float2half_rn(x.w);
    *(uint2*)dst = o.u;
}

// =====================================================================
// Kernel 2: embed + input-gate GEMM via HMMA fp16 (proven R15).
// =====================================================================
#define XCHK 64
#define XNCH (H_SZ / XCHK)        // 8
#define XSTAGES 3
#define XTILE_B (128 * 128)
#define XSTAGE_B (2 * XTILE_B)
#define XTOT_B (XSTAGES * XSTAGE_B)

__global__ __launch_bounds__(256, 2)
void embed_mma_kernel(const float* __restrict__ b_ih,
                      const int*   __restrict__ target)
{
    extern __shared__ __align__(128) char xsm[];
    const uint32_t smb = smem_u32(xsm);
    const int tid  = threadIdx.x;
    const int wid  = tid >> 5;
    const int lane = tid & 31;
    const int warp_m = wid >> 2;
    const int warp_n = wid & 3;
    const int m0 = blockIdx.x * 128;
    const int n0 = blockIdx.y * 128;

    const int lrw = tid >> 1;
    const int lsb = (tid & 1) * 4;

    const int mrow = m0 + lrw;
    const int trow = mrow & (T_SEQ - 1);
    const int tok  = trow ? __ldg(target + mrow - 1) : 1;
    const __half* arow = g_bh + (size_t)tok * H_SZ;
    const __half* brow = g_wh + (size_t)(n0 + lrw) * H_SZ;

    float c[4][4][4];
#pragma unroll
    for (int i = 0; i < 4; i++)
#pragma unroll
        for (int j = 0; j < 4; j++)
#pragma unroll
            for (int q = 0; q < 4; q++) c[i][j][q] = 0.0f;

    const int lrow = lane & 15;
    const int lkh  = lane >> 4;

    auto issue = [&](int ch, int st) {
        uint32_t As = smb + st * XSTAGE_B;
        uint32_t Bs = As + XTILE_B;
        const int kb = ch * XCHK;
#pragma unroll
        for (int i2 = 0; i2 < 4; i2++) {
            int seg = lsb + i2;
            cp_async16(As + swoff(lrw, seg), arow + kb + seg * 8);
            cp_async16(Bs + swoff(lrw, seg), brow + kb + seg * 8);
        }
    };

    issue(0, 0); cp_commit();
    issue(1, 1); cp_commit();

    for (int ch = 0; ch < XNCH; ch++) {
        cp_wait1();
        __syncthreads();

        int chn = ch + 2;
        if (chn < XNCH) issue(chn, chn % XSTAGES);
        cp_commit();

        uint32_t As = smb + (ch % XSTAGES) * XSTAGE_B;
        uint32_t Bs = As + XTILE_B;
#pragma unroll
        for (int ks = 0; ks < 4; ks++) {
            const int seg = ks * 2 + lkh;
            uint32_t a[4][4], bf[2][4];
#pragma unroll
            for (int mt = 0; mt < 4; mt++)
                ldsm4(a[mt], As + swoff(warp_m * 64 + mt * 16 + lrow, seg));
#pragma unroll
            for (int ng = 0; ng < 2; ng++)
                ldsm4(bf[ng], Bs + swoff(warp_n * 32 + ng * 16 + lrow, seg));
#pragma unroll
            for (int mt = 0; mt < 4; mt++)
#pragma unroll
                for (int nt = 0; nt < 4; nt++) {
                    uint32_t* bv = bf[nt >> 1];
                    mma16816h(c[mt][nt], a[mt], bv[nt & 1], bv[(nt & 1) + 2]);
                }
        }
        __syncthreads();
    }

    const int rr   = lane >> 2;
    const int col2 = (lane & 3) * 2;
    const int ncol0 = n0 + warp_n * 32;
    float2 bo[4];
#pragma unroll
    for (int nt = 0; nt < 4; nt++) {
        bo[nt].x = __ldg(b_ih + ncol0 + nt * 8 + col2);
        bo[nt].y = __ldg(b_ih + ncol0 + nt * 8 + col2 + 1);
    }
#pragma unroll
    for (int mt = 0; mt < 4; mt++) {
#pragma unroll
        for (int half = 0; half < 2; half++) {
            int m = m0 + warp_m * 64 + mt * 16 + rr + half * 8;
            float* dst = g_xg + (size_t)m * G3 + ncol0;
#pragma unroll
            for (int nt = 0; nt < 4; nt++) {
                int nc = nt * 8 + col2;
                float2 v;
                v.x = c[mt][nt][half * 2 + 0] + bo[nt].x;
                v.y = c[mt][nt][half * 2 + 1] + bo[nt].y;
                *(float2*)(dst + nc) = v;
            }
        }
    }
}

// =====================================================================
// Reset kernel (graph-replay determinism)
// =====================================================================
__global__ void reset_bar_kernel() {
    int t = threadIdx.x;
    if (t < NBAR) g_bars[t * BARSTRIDE] = 0u;
    if (t == 8)  g_job = 0u;
    if (t == 9)  g_tdone = 0u;
}

// =====================================================================
// FUSED persistent kernel: 148 CTAs x 512 threads.
//   CTAs 0..63: GRU (8 H dims each, k-split 2), then join workers.
//   CTAs 64..147 (84): logits workers from the start.
// =====================================================================
#define NGRU 64
#define NCTA_FUSED 148
#define WPAD 520
#define HPAD 516
#define PPAD 9            // part row stride (gcd(9,32)=1 -> conflict-free)

// logits worker tile config (proven R13/R15)
#define LMT 128
#define LNT 256
#define CHK 64
#define NCH (H_SZ / CHK)          // 8
#define LSTAGES 3
#define ATILE_B (128 * 128)
#define BTILE_B (256 * 128)
#define STAGE_B (ATILE_B + BTILE_B)   // 49152
#define LTOT_B (LSTAGES * STAGE_B)    // 147456
#define NB_M (M_ROWS / LMT)       // 32
#define NB_N (V_SZ / LNT)         // 125
#define NJOBS (NB_M * NB_N)       // 4000

#define FUSED_SMEM_BYTES LTOT_B   // 147456 >= GRU smem need (124160)

// One 128x256 logits tile; all 512 threads active.
static __device__ void logits_tile(int m0, int n0, uint32_t smb,
                                   const float* __restrict__ b_out,
                                   float* __restrict__ out)
{
    const int tid  = threadIdx.x;
    const int wid  = tid >> 5;
    const int lane = tid & 31;
    const int warp_m = wid >> 3;
    const int warp_n = wid & 7;

    float c[4][4][4];
#pragma unroll
    for (int i = 0; i < 4; i++)
#pragma unroll
        for (int j = 0; j < 4; j++)
#pragma unroll
            for (int q = 0; q < 4; q++) c[i][j][q] = 0.0f;

    const int lrow = lane & 15;
    const int lkh  = lane >> 4;

    const __half* abase = g_ah + (size_t)m0 * H_SZ;
    const __half* bbase = g_bh + (size_t)n0 * H_SZ;

    auto issue = [&](int ch, int st) {
        uint32_t As = smb + st * STAGE_B;
        uint32_t Bs = As + ATILE_B;
        const int kb = ch * CHK;
#pragma unroll
        for (int l = 0; l < 2; l++) {
            int s   = tid + l * 512;
            int row = s >> 3;
            int seg = s & 7;
            cp_async16(As + swoff(row, seg),
                       abase + (size_t)row * H_SZ + kb + seg * 8);
        }
#pragma unroll
        for (int l = 0; l < 4; l++) {
            int s   = tid + l * 512;
            int row = s >> 3;
            int seg = s & 7;
            cp_async16(Bs + swoff(row, seg),
                       bbase + (size_t)row * H_SZ + kb + seg * 8);
        }
    };

    issue(0, 0); cp_commit();
    issue(1, 1); cp_commit();

    for (int ch = 0; ch < NCH; ch++) {
        cp_wait1();
        __syncthreads();

        int chn = ch + 2;
        if (chn < NCH) issue(chn, chn % LSTAGES);
        cp_commit();

        uint32_t As = smb + (ch % LSTAGES) * STAGE_B;
        uint32_t Bs = As + ATILE_B;
#pragma unroll
        for (int ks = 0; ks < 4; ks++) {
            const int seg = ks * 2 + lkh;
            uint32_t a[4][4], bf[2][4];
#pragma unroll
            for (int mt = 0; mt < 4; mt++)
                ldsm4(a[mt], As + swoff(warp_m * 64 + mt * 16 + lrow, seg));
#pragma unroll
            for (int ng = 0; ng < 2; ng++)
                ldsm4(bf[ng], Bs + swoff(warp_n * 32 + ng * 16 + lrow, seg));
#pragma unroll
            for (int mt = 0; mt < 4; mt++)
#pragma unroll
                for (int nt = 0; nt < 4; nt++) {
                    uint32_t* bv = bf[nt >> 1];
                    mma16816h(c[mt][nt], a[mt], bv[nt & 1], bv[(nt & 1) + 2]);
                }
        }
        __syncthreads();
    }

    const int rr   = lane >> 2;
    const int col2 = (lane & 3) * 2;
    const int ncol0 = n0 + warp_n * 32;
    float2 bo[4];
#pragma unroll
    for (int nt = 0; nt < 4; nt++) {
        bo[nt].x = __ldg(b_out + ncol0 + nt * 8 + col2);
        bo[nt].y = __ldg(b_out + ncol0 + nt * 8 + col2 + 1);
    }
#pragma unroll
    for (int mt = 0; mt < 4; mt++) {
#pragma unroll
        for (int half = 0; half < 2; half++) {
            int m = m0 + warp_m * 64 + mt * 16 + rr + half * 8;
            int bb2 = m & 31;
            int tt  = m >> 5;
            float* dst = out + ((size_t)bb2 * T_SEQ + tt) * V_SZ + ncol0;
#pragma unroll
            for (int nt = 0; nt < 4; nt++) {
                int nc = nt * 8 + col2;
                float2 v;
                v.x = c[mt][nt][half * 2 + 0] + bo[nt].x;
                v.y = c[mt][nt][half * 2 + 1] + bo[nt].y;
                *(float2*)(dst + nc) = v;
            }
        }
    }
}

__global__ __launch_bounds__(512, 1)
void fused_kernel(const float* __restrict__ w_hh,
                  const float* __restrict__ b_hh,
                  const float* __restrict__ enc,
                  const float* __restrict__ b_out,
                  float* __restrict__ out)
{
    extern __shared__ __align__(128) char fsm[];
    const int cta = blockIdx.x;
    const int tid = threadIdx.x;

    // ---------------- GRU role (CTAs 0..63) ----------------
    if (cta < NGRU) {
        float* dsm  = (float*)fsm;
        float* ws   = dsm;                           // 24 * WPAD
        float* hsm  = dsm + 24 * WPAD;               // 32 * HPAD
        float* part = dsm + 24 * WPAD + 32 * HPAD;   // [256][PPAD]

        // Load 24 w_hh rows (3072 float4 slots / 512 threads = 6 iters)
#pragma unroll
        for (int l = 0; l < 6; l++) {
            int idx = tid + l * 512;
            int rr  = idx >> 7;              // 0..23
            int cc  = (idx & 127) << 2;
            int gate = rr >> 3;              // 0..2
            int il2  = rr & 7;
            int grow = gate * H_SZ + cta * 8 + il2;
            *(float4*)&ws[rr * WPAD + cc] =
                *(const float4*)(w_hh + (size_t)grow * H_SZ + cc);
        }

        const int kh = tid >> 8;        // 0..1 k-split
        const int r  = tid & 255;       // (b, il)
        const int b  = r >> 3;
        const int il = r & 7;
        const int i  = cta * 8 + il;
        const int kbase = kh << 8;      // 0 or 256

        const float bhr = b_hh[i];
        const float bhz = b_hh[H_SZ + i];
        const float bhn = b_hh[2 * H_SZ + i];

        const ulonglong2* wr = (const ulonglong2*)&ws[(0  + il) * WPAD + kbase];
        const ulonglong2* wz = (const ulonglong2*)&ws[(8  + il) * WPAD + kbase];
        const ulonglong2* wn = (const ulonglong2*)&ws[(16 + il) * WPAD + kbase];

        for (int t = 0; t < T_SEQ; t++) {
            const float* hsrc = (t == 0) ? enc
                              : (g_hs + (size_t)(t - 1) * B_SZ * H_SZ);
            __syncthreads();
#pragma unroll
            for (int j = 0; j < 8; j++) {
                int s  = tid + j * 512;
                int bb = s >> 7;
                int k4 = (s & 127) << 2;
                float4 v = __ldcg((const float4*)(hsrc + (size_t)bb * H_SZ + k4));
                *(float4*)&hsm[bb * HPAD + k4] = v;
            }
            // xg prefetch (hide L2 latency under the FFMA2 stream)
            float xr = 0.0f, xz = 0.0f, xn = 0.0f;
            if (tid < 256) {
                const float* xgp = g_xg + ((size_t)b * T_SEQ + t) * G3;
                xr = __ldg(xgp + i);
                xz = __ldg(xgp + H_SZ + i);
                xn = __ldg(xgp + 2 * H_SZ + i);
            }
            __syncthreads();

            const float* hp = &hsm[b * HPAD + kbase];
            unsigned long long ar0 = 0ull, ar1 = 0ull;
            unsigned long long az0 = 0ull, az1 = 0ull;
            unsigned long long an0 = 0ull, an1 = 0ull;
#pragma unroll 16
            for (int k = 0; k < 256; k += 8) {
                ulonglong2 h01 = *(const ulonglong2*)(hp + k);
                ulonglong2 h23 = *(const ulonglong2*)(hp + k + 4);
                ulonglong2 w_r0 = wr[(k >> 2) + 0];
                ulonglong2 w_r1 = wr[(k >> 2) + 1];
                ulonglong2 w_z0 = wz[(k >> 2) + 0];
                ulonglong2 w_z1 = wz[(k >> 2) + 1];
                ulonglong2 w_n0 = wn[(k >> 2) + 0];
                ulonglong2 w_n1 = wn[(k >> 2) + 1];
                ar0 = f2fma(h01.x, w_r0.x, ar0);
                ar1 = f2fma(h01.y, w_r0.y, ar1);
                ar0 = f2fma(h23.x, w_r1.x, ar0);
                ar1 = f2fma(h23.y, w_r1.y, ar1);
                az0 = f2fma(h01.x, w_z0.x, az0);
                az1 = f2fma(h01.y, w_z0.y, az1);
                az0 = f2fma(h23.x, w_z1.x, az0);
                az1 = f2fma(h23.y, w_z1.y, az1);
                an0 = f2fma(h01.x, w_n0.x, an0);
                an1 = f2fma(h01.y, w_n0.y, an1);
                an0 = f2fma(h23.x, w_n1.x, an0);
                an1 = f2fma(h23.y, w_n1.y, an1);
            }
            float2 pr0 = upk2(ar0), pr1 = upk2(ar1);
            float2 pz0 = upk2(az0), pz1 = upk2(az1);
            float2 pn0 = upk2(an0), pn1 = upk2(an1);
            float* pp = &part[r * PPAD + kh * 4];
            pp[0] = (pr0.x + pr0.y) + (pr1.x + pr1.y);
            pp[1] = (pz0.x + pz0.y) + (pz1.x + pz1.y);
            pp[2] = (pn0.x + pn0.y) + (pn1.x + pn1.y);
            __syncthreads();

            if (tid < 256) {
                const float* pr = &part[r * PPAD];
                float hr = pr[0] + pr[4] + bhr;
                float hz = pr[1] + pr[5] + bhz;
                float hn = pr[2] + pr[6] + bhn;

                float rg = sigmoidf_(xr + hr);
                float zg = sigmoidf_(xz + hz);
                float ng = tanhf(xn + rg * hn);
                float h_new = (1.0f - zg) * ng + zg * hsm[b * HPAD + i];

                g_hs[((size_t)t * B_SZ + b) * H_SZ + i] = h_new;
                g_ah[((size_t)t * B_SZ + b) * H_SZ + i] = __float2half_rn(h_new);
            }

            // grid barrier over the 64 GRU CTAs (8 split counters of 8)
            __syncthreads();
            if (tid == 0) {
                __threadfence();
                atomicAdd(&g_bars[(cta & (NBAR - 1)) * BARSTRIDE], 1u);
            }
            if (tid < 32) {
                const unsigned need = (unsigned)((NGRU / NBAR) * (t + 1));
                bool ok;
                do {
                    unsigned v = (tid < NBAR) ? ld_acq(&g_bars[tid * BARSTRIDE])
                                              : need;
                    ok = (v >= need);
                } while (__ballot_sync(0xffffffffu, ok) != 0xffffffffu);
            }
            // publish progress for the logits workers (single line)
            if (cta == 0 && tid == 0) st_rel(&g_tdone, (unsigned)(t + 1));
            __syncthreads();
        }
    }

    // ---------------- worker role (all CTAs) ----------------
    const uint32_t smb = smem_u32(fsm);
    __shared__ unsigned sjob;
    for (;;) {
        if (tid == 0) sjob = atomicAdd(&g_job, 1u);
        __syncthreads();
        unsigned j = sjob;
        __syncthreads();   // sjob consumed before next overwrite
        if (j >= (unsigned)NJOBS) break;
        int mb = (int)(j / NB_N);
        int nb = (int)(j % NB_N);
        // rows m0..m0+127 cover t in [mb*4, mb*4+3] -> need mb*4+4 steps done
        if (tid == 0) {
            unsigned need = (unsigned)(mb * 4 + 4);
            while (ld_acq(&g_tdone) < need) nsleep(128);
        }
        __syncthreads();
        logits_tile(mb * LMT, nb * LNT, smb, b_out, out);
        __syncthreads();
    }
}

// =====================================================================
// kernel_launch: convert -> embed_mma -> reset -> fused (4 launches)
// =====================================================================
extern "C" void kernel_launch(void* const* d_in, const int* in_sizes, int n_in,
                              void* d_out, int out_size)
{
    const float* emb    = (const float*)d_in[0];  // [V, H]
    const float* w_ih   = (const float*)d_in[1];  // [3H, H]
    const float* w_hh   = (const float*)d_in[2];  // [3H, H]
    const float* b_ih   = (const float*)d_in[3];  // [3H]
    const float* b_hh   = (const float*)d_in[4];  // [3H]
    const float* b_out  = (const float*)d_in[5];  // [V]
    const float* enc    = (const float*)d_in[6];  // [1, B, H]
    const int*   target = (const int*)d_in[7];    // [B, T]
    float* out = (float*)d_out;                   // [B, T, V]

    (void)in_sizes; (void)n_in; (void)out_size;

    static bool attr_done = false;
    if (!attr_done) {
        cudaFuncSetAttribute(embed_mma_kernel,
                             cudaFuncAttributeMaxDynamicSharedMemorySize, XTOT_B);
        cudaFuncSetAttribute(fused_kernel,
                             cudaFuncAttributeMaxDynamicSharedMemorySize,
                             FUSED_SMEM_BYTES);
        attr_done = true;
    }

    convert_kernel<<<CONV_GRID, 256>>>(emb, w_ih);

    embed_mma_kernel<<<dim3(M_ROWS / 128, G3 / 128), 256, XTOT_B>>>(b_ih, target);

    reset_bar_kernel<<<1, 32>>>();

    fused_kernel<<<NCTA_FUSED, 512, FUSED_SMEM_BYTES>>>(
        w_hh, b_hh, enc, b_out, out);
}

// round 17
// speedup vs baseline: 1.7245x; 1.7245x over previous
#include <cuda_runtime.h>
#include <cuda_fp16.h>
#include <math.h>
#include <stdint.h>

// Problem constants
#define T_SEQ 128
#define B_SZ  32
#define H_SZ  512
#define V_SZ  32000
#define G3    1536          // 3*H
#define M_ROWS 4096         // B*T

// Scratch (device globals: allocation-free rule)
__device__ __align__(16) float g_xg[(size_t)M_ROWS * G3];          // [m=b*T+t][3H]
__device__ __align__(16) float g_hs[(size_t)T_SEQ * B_SZ * H_SZ];  // [t][b][h]
__device__ __align__(16) __half g_ah[(size_t)M_ROWS * H_SZ];       // A fp16 [m][512]
__device__ __align__(16) __half g_bh[(size_t)V_SZ * H_SZ];         // emb fp16 [v][512]
__device__ __align__(16) __half g_wh[(size_t)G3 * H_SZ];           // w_ih fp16 [g][512]
#define NBAR 8
#define BARSTRIDE 64
__device__ unsigned g_bars[NBAR * BARSTRIDE];
__device__ unsigned g_job;     // logits tile job counter
__device__ unsigned g_tdone;   // GRU progress (steps complete), release-published

// ---------- packed fp32x2 helpers ----------
static __device__ __forceinline__ unsigned long long f2fma(unsigned long long a,
                                                           unsigned long long b,
                                                           unsigned long long c) {
    unsigned long long d;
    asm("fma.rn.f32x2 %0, %1, %2, %3;" : "=l"(d) : "l"(a), "l"(b), "l"(c));
    return d;
}
static __device__ __forceinline__ float2 upk2(unsigned long long v) {
    float2 r;
    asm("mov.b64 {%0, %1}, %2;" : "=f"(r.x), "=f"(r.y) : "l"(v));
    return r;
}
static __device__ __forceinline__ float sigmoidf_(float x) {
    return 1.0f / (1.0f + expf(-x));
}
static __device__ __forceinline__ unsigned ld_acq(const unsigned* p) {
    unsigned v;
    asm volatile("ld.global.acquire.gpu.u32 %0, [%1];" : "=r"(v) : "l"(p) : "memory");
    return v;
}
static __device__ __forceinline__ void st_rel(unsigned* p, unsigned v) {
    asm volatile("st.global.release.gpu.u32 [%0], %1;" :: "l"(p), "r"(v) : "memory");
}
static __device__ __forceinline__ void nsleep(unsigned ns) {
    asm volatile("nanosleep.u32 %0;" :: "r"(ns));
}

// ---------- smem / async-copy / mma helpers (baseline PTX only) ----------
static __device__ __forceinline__ uint32_t smem_u32(const void* p) {
    uint32_t a;
    asm("{ .reg .u64 t; cvta.to.shared.u64 t, %1; cvt.u32.u64 %0, t; }"
        : "=r"(a) : "l"(p));
    return a;
}
static __device__ __forceinline__ void cp_async16(uint32_t dst, const void* src) {
    asm volatile("cp.async.cg.shared.global [%0], [%1], 16;" :: "r"(dst), "l"(src));
}
static __device__ __forceinline__ void cp_commit() {
    asm volatile("cp.async.commit_group;");
}
static __device__ __forceinline__ void cp_wait1() {
    asm volatile("cp.async.wait_group 1;" ::: "memory");
}
static __device__ __forceinline__ void ldsm4(uint32_t* r, uint32_t addr) {
    asm volatile("ldmatrix.sync.aligned.m8n8.x4.shared.b16 {%0,%1,%2,%3}, [%4];"
                 : "=r"(r[0]), "=r"(r[1]), "=r"(r[2]), "=r"(r[3]) : "r"(addr));
}
static __device__ __forceinline__ void mma16816h(float* c, const uint32_t* a,
                                                 uint32_t b0, uint32_t b1) {
    asm volatile(
        "mma.sync.aligned.m16n8k16.row.col.f32.f16.f16.f32 "
        "{%0,%1,%2,%3}, {%4,%5,%6,%7}, {%8,%9}, {%0,%1,%2,%3};"
        : "+f"(c[0]), "+f"(c[1]), "+f"(c[2]), "+f"(c[3])
        : "r"(a[0]), "r"(a[1]), "r"(a[2]), "r"(a[3]), "r"(b0), "r"(b1));
}

// 128B rows, seg 0..7 (16B units), classic SW128: seg' = seg ^ (row&7).
static __device__ __forceinline__ uint32_t swoff(int row, int seg) {
    return (uint32_t)((row << 7) + (((seg ^ row) & 7) << 4));
}

// =====================================================================
// Kernel 1: convert — emb fp32->fp16 (g_bh) and w_ih fp32->fp16 (g_wh)
// =====================================================================
union HF4 { __half h[4]; uint2 u; };

#define EMB_CONV_SLOTS (V_SZ * (H_SZ / 4))
#define WIH_CONV_SLOTS (G3 * (H_SZ / 4))
#define CONV_TOTAL (EMB_CONV_SLOTS + WIH_CONV_SLOTS)
#define CONV_GRID ((CONV_TOTAL + 255) / 256)

__global__ __launch_bounds__(256)
void convert_kernel(const float* __restrict__ emb,
                    const float* __restrict__ w_ih)
{
    int s = blockIdx.x * 256 + threadIdx.x;
    const float* src;
    __half* dst;
    if (s < EMB_CONV_SLOTS) {
        src = emb + (size_t)s * 4;
        dst = g_bh + (size_t)s * 4;
    } else {
        int s2 = s - EMB_CONV_SLOTS;
        if (s2 >= WIH_CONV_SLOTS) return;
        src = w_ih + (size_t)s2 * 4;
        dst = g_wh + (size_t)s2 * 4;
    }
    float4 x = *(const float4*)src;
    HF4 o;
    o.h[0] = __float2half_rn(x.x);
    o.h[1] = __float2half_rn(x.y);
    o.h[2] = __float2half_rn(x.z);
    o.h[3] = __float2half_rn(x.w);
    *(uint2*)dst = o.u;
}

// =====================================================================
// Kernel 2: embed + input-gate GEMM via HMMA fp16 (proven R15).
// =====================================================================
#define XCHK 64
#define XNCH (H_SZ / XCHK)        // 8
#define XSTAGES 3
#define XTILE_B (128 * 128)
#define XSTAGE_B (2 * XTILE_B)
#define XTOT_B (XSTAGES * XSTAGE_B)

__global__ __launch_bounds__(256, 2)
void embed_mma_kernel(const float* __restrict__ b_ih,
                      const int*   __restrict__ target)
{
    extern __shared__ __align__(128) char xsm[];
    const uint32_t smb = smem_u32(xsm);
    const int tid  = threadIdx.x;
    const int wid  = tid >> 5;
    const int lane = tid & 31;
    const int warp_m = wid >> 2;
    const int warp_n = wid & 3;
    const int m0 = blockIdx.x * 128;
    const int n0 = blockIdx.y * 128;

    const int lrw = tid >> 1;
    const int lsb = (tid & 1) * 4;

    const int mrow = m0 + lrw;
    const int trow = mrow & (T_SEQ - 1);
    const int tok  = trow ? __ldg(target + mrow - 1) : 1;
    const __half* arow = g_bh + (size_t)tok * H_SZ;
    const __half* brow = g_wh + (size_t)(n0 + lrw) * H_SZ;

    float c[4][4][4];
#pragma unroll
    for (int i = 0; i < 4; i++)
#pragma unroll
        for (int j = 0; j < 4; j++)
#pragma unroll
            for (int q = 0; q < 4; q++) c[i][j][q] = 0.0f;

    const int lrow = lane & 15;
    const int lkh  = lane >> 4;

    auto issue = [&](int ch, int st) {
        uint32_t As = smb + st * XSTAGE_B;
        uint32_t Bs = As + XTILE_B;
        const int kb = ch * XCHK;
#pragma unroll
        for (int i2 = 0; i2 < 4; i2++) {
            int seg = lsb + i2;
            cp_async16(As + swoff(lrw, seg), arow + kb + seg * 8);
            cp_async16(Bs + swoff(lrw, seg), brow + kb + seg * 8);
        }
    };

    issue(0, 0); cp_commit();
    issue(1, 1); cp_commit();

    for (int ch = 0; ch < XNCH; ch++) {
        cp_wait1();
        __syncthreads();

        int chn = ch + 2;
        if (chn < XNCH) issue(chn, chn % XSTAGES);
        cp_commit();

        uint32_t As = smb + (ch % XSTAGES) * XSTAGE_B;
        uint32_t Bs = As + XTILE_B;
#pragma unroll
        for (int ks = 0; ks < 4; ks++) {
            const int seg = ks * 2 + lkh;
            uint32_t a[4][4], bf[2][4];
#pragma unroll
            for (int mt = 0; mt < 4; mt++)
                ldsm4(a[mt], As + swoff(warp_m * 64 + mt * 16 + lrow, seg));
#pragma unroll
            for (int ng = 0; ng < 2; ng++)
                ldsm4(bf[ng], Bs + swoff(warp_n * 32 + ng * 16 + lrow, seg));
#pragma unroll
            for (int mt = 0; mt < 4; mt++)
#pragma unroll
                for (int nt = 0; nt < 4; nt++) {
                    uint32_t* bv = bf[nt >> 1];
                    mma16816h(c[mt][nt], a[mt], bv[nt & 1], bv[(nt & 1) + 2]);
                }
        }
        __syncthreads();
    }

    const int rr   = lane >> 2;
    const int col2 = (lane & 3) * 2;
    const int ncol0 = n0 + warp_n * 32;
    float2 bo[4];
#pragma unroll
    for (int nt = 0; nt < 4; nt++) {
        bo[nt].x = __ldg(b_ih + ncol0 + nt * 8 + col2);
        bo[nt].y = __ldg(b_ih + ncol0 + nt * 8 + col2 + 1);
    }
#pragma unroll
    for (int mt = 0; mt < 4; mt++) {
#pragma unroll
        for (int half = 0; half < 2; half++) {
            int m = m0 + warp_m * 64 + mt * 16 + rr + half * 8;
            float* dst = g_xg + (size_t)m * G3 + ncol0;
#pragma unroll
            for (int nt = 0; nt < 4; nt++) {
                int nc = nt * 8 + col2;
                float2 v;
                v.x = c[mt][nt][half * 2 + 0] + bo[nt].x;
                v.y = c[mt][nt][half * 2 + 1] + bo[nt].y;
                *(float2*)(dst + nc) = v;
            }
        }
    }
}

// =====================================================================
// Reset kernel (graph-replay determinism)
// =====================================================================
__global__ void reset_bar_kernel() {
    int t = threadIdx.x;
    if (t < NBAR) g_bars[t * BARSTRIDE] = 0u;
    if (t == 8)  g_job = 0u;
    if (t == 9)  g_tdone = 0u;
}

// =====================================================================
// FUSED persistent kernel: 148 CTAs x 512 threads (R15 proven shape).
//   CTAs 0..127: GRU (4 H dims, k-split 4), then join workers.
//   CTAs 128..147: logits workers from the start.
// =====================================================================
#define NGRU 128
#define NCTA_FUSED 148
#define WPAD 520
#define HPAD 516
#define PPAD 17           // part row stride (odd -> conflict-free)

// logits worker tile config (proven R13/R15)
#define LMT 128
#define LNT 256
#define CHK 64
#define NCH (H_SZ / CHK)          // 8
#define LSTAGES 3
#define ATILE_B (128 * 128)
#define BTILE_B (256 * 128)
#define STAGE_B (ATILE_B + BTILE_B)   // 49152
#define LTOT_B (LSTAGES * STAGE_B)    // 147456
#define NB_M (M_ROWS / LMT)       // 32
#define NB_N (V_SZ / LNT)         // 125
#define NJOBS (NB_M * NB_N)       // 4000

#define FUSED_SMEM_BYTES LTOT_B   // 147456 >= GRU smem need

// One 128x256 logits tile; all 512 threads active.
static __device__ void logits_tile(int m0, int n0, uint32_t smb,
                                   const float* __restrict__ b_out,
                                   float* __restrict__ out)
{
    const int tid  = threadIdx.x;
    const int wid  = tid >> 5;
    const int lane = tid & 31;
    const int warp_m = wid >> 3;
    const int warp_n = wid & 7;

    float c[4][4][4];
#pragma unroll
    for (int i = 0; i < 4; i++)
#pragma unroll
        for (int j = 0; j < 4; j++)
#pragma unroll
            for (int q = 0; q < 4; q++) c[i][j][q] = 0.0f;

    const int lrow = lane & 15;
    const int lkh  = lane >> 4;

    const __half* abase = g_ah + (size_t)m0 * H_SZ;
    const __half* bbase = g_bh + (size_t)n0 * H_SZ;

    auto issue = [&](int ch, int st) {
        uint32_t As = smb + st * STAGE_B;
        uint32_t Bs = As + ATILE_B;
        const int kb = ch * CHK;
#pragma unroll
        for (int l = 0; l < 2; l++) {
            int s   = tid + l * 512;
            int row = s >> 3;
            int seg = s & 7;
            cp_async16(As + swoff(row, seg),
                       abase + (size_t)row * H_SZ + kb + seg * 8);
        }
#pragma unroll
        for (int l = 0; l < 4; l++) {
            int s   = tid + l * 512;
            int row = s >> 3;
            int seg = s & 7;
            cp_async16(Bs + swoff(row, seg),
                       bbase + (size_t)row * H_SZ + kb + seg * 8);
        }
    };

    issue(0, 0); cp_commit();
    issue(1, 1); cp_commit();

    for (int ch = 0; ch < NCH; ch++) {
        cp_wait1();
        __syncthreads();

        int chn = ch + 2;
        if (chn < NCH) issue(chn, chn % LSTAGES);
        cp_commit();

        uint32_t As = smb + (ch % LSTAGES) * STAGE_B;
        uint32_t Bs = As + ATILE_B;
#pragma unroll
        for (int ks = 0; ks < 4; ks++) {
            const int seg = ks * 2 + lkh;
            uint32_t a[4][4], bf[2][4];
#pragma unroll
            for (int mt = 0; mt < 4; mt++)
                ldsm4(a[mt], As + swoff(warp_m * 64 + mt * 16 + lrow, seg));
#pragma unroll
            for (int ng = 0; ng < 2; ng++)
                ldsm4(bf[ng], Bs + swoff(warp_n * 32 + ng * 16 + lrow, seg));
#pragma unroll
            for (int mt = 0; mt < 4; mt++)
#pragma unroll
                for (int nt = 0; nt < 4; nt++) {
                    uint32_t* bv = bf[nt >> 1];
                    mma16816h(c[mt][nt], a[mt], bv[nt & 1], bv[(nt & 1) + 2]);
                }
        }
        __syncthreads();
    }

    const int rr   = lane >> 2;
    const int col2 = (lane & 3) * 2;
    const int ncol0 = n0 + warp_n * 32;
    float2 bo[4];
#pragma unroll
    for (int nt = 0; nt < 4; nt++) {
        bo[nt].x = __ldg(b_out + ncol0 + nt * 8 + col2);
        bo[nt].y = __ldg(b_out + ncol0 + nt * 8 + col2 + 1);
    }
#pragma unroll
    for (int mt = 0; mt < 4; mt++) {
#pragma unroll
        for (int half = 0; half < 2; half++) {
            int m = m0 + warp_m * 64 + mt * 16 + rr + half * 8;
            int bb2 = m & 31;
            int tt  = m >> 5;
            float* dst = out + ((size_t)bb2 * T_SEQ + tt) * V_SZ + ncol0;
#pragma unroll
            for (int nt = 0; nt < 4; nt++) {
                int nc = nt * 8 + col2;
                float2 v;
                v.x = c[mt][nt][half * 2 + 0] + bo[nt].x;
                v.y = c[mt][nt][half * 2 + 1] + bo[nt].y;
                *(float2*)(dst + nc) = v;
            }
        }
    }
}

__global__ __launch_bounds__(512, 1)
void fused_kernel(const float* __restrict__ w_hh,
                  const float* __restrict__ b_hh,
                  const float* __restrict__ enc,
                  const float* __restrict__ b_out,
                  float* __restrict__ out)
{
    extern __shared__ __align__(128) char fsm[];
    const int cta = blockIdx.x;
    const int tid = threadIdx.x;

    // ---------------- GRU role (CTAs 0..127) ----------------
    if (cta < NGRU) {
        float* dsm  = (float*)fsm;
        float* ws   = dsm;                           // 12 * WPAD
        float* hsm  = dsm + 12 * WPAD;               // 32 * HPAD
        float* part = dsm + 12 * WPAD + 32 * HPAD;   // [128][PPAD]

#pragma unroll
        for (int l = 0; l < 3; l++) {
            int idx = tid + l * 512;
            int rr  = idx >> 7;
            int cc  = (idx & 127) << 2;
            int gate = rr >> 2;
            int il2  = rr & 3;
            int grow = gate * H_SZ + cta * 4 + il2;
            *(float4*)&ws[rr * WPAD + cc] =
                *(const float4*)(w_hh + (size_t)grow * H_SZ + cc);
        }

        const int kh = tid >> 7;
        const int r  = tid & 127;
        const int b  = r >> 2;
        const int il = r & 3;
        const int i  = cta * 4 + il;
        const int kbase = kh << 7;

        const float bhr = b_hh[i];
        const float bhz = b_hh[H_SZ + i];
        const float bhn = b_hh[2 * H_SZ + i];

        const ulonglong2* wr = (const ulonglong2*)&ws[(0 + il) * WPAD + kbase];
        const ulonglong2* wz = (const ulonglong2*)&ws[(4 + il) * WPAD + kbase];
        const ulonglong2* wn = (const ulonglong2*)&ws[(8 + il) * WPAD + kbase];

        for (int t = 0; t < T_SEQ; t++) {
            const float* hsrc = (t == 0) ? enc
                              : (g_hs + (size_t)(t - 1) * B_SZ * H_SZ);
            __syncthreads();
#pragma unroll
            for (int j = 0; j < 8; j++) {
                int s  = tid + j * 512;
                int bb = s >> 7;
                int k4 = (s & 127) << 2;
                float4 v = __ldcg((const float4*)(hsrc + (size_t)bb * H_SZ + k4));
                *(float4*)&hsm[bb * HPAD + k4] = v;
            }
            // xg prefetch: hide L2 latency under the FFMA2 stream.
            float xr = 0.0f, xz = 0.0f, xn = 0.0f;
            if (tid < 128) {
                const float* xgp = g_xg + ((size_t)b * T_SEQ + t) * G3;
                xr = __ldg(xgp + i);
                xz = __ldg(xgp + H_SZ + i);
                xn = __ldg(xgp + 2 * H_SZ + i);
            }
            __syncthreads();

            const float* hp = &hsm[b * HPAD + kbase];
            unsigned long long ar0 = 0ull, ar1 = 0ull;
            unsigned long long az0 = 0ull, az1 = 0ull;
            unsigned long long an0 = 0ull, an1 = 0ull;
#pragma unroll
            for (int k = 0; k < 128; k += 8) {
                ulonglong2 h01 = *(const ulonglong2*)(hp + k);
                ulonglong2 h23 = *(const ulonglong2*)(hp + k + 4);
                ulonglong2 w_r0 = wr[(k >> 2) + 0];
                ulonglong2 w_r1 = wr[(k >> 2) + 1];
                ulonglong2 w_z0 = wz[(k >> 2) + 0];
                ulonglong2 w_z1 = wz[(k >> 2) + 1];
                ulonglong2 w_n0 = wn[(k >> 2) + 0];
                ulonglong2 w_n1 = wn[(k >> 2) + 1];
                ar0 = f2fma(h01.x, w_r0.x, ar0);
                ar1 = f2fma(h01.y, w_r0.y, ar1);
                ar0 = f2fma(h23.x, w_r1.x, ar0);
                ar1 = f2fma(h23.y, w_r1.y, ar1);
                az0 = f2fma(h01.x, w_z0.x, az0);
                az1 = f2fma(h01.y, w_z0.y, az1);
                az0 = f2fma(h23.x, w_z1.x, az0);
                az1 = f2fma(h23.y, w_z1.y, az1);
                an0 = f2fma(h01.x, w_n0.x, an0);
                an1 = f2fma(h01.y, w_n0.y, an1);
                an0 = f2fma(h23.x, w_n1.x, an0);
                an1 = f2fma(h23.y, w_n1.y, an1);
            }
            float2 pr0 = upk2(ar0), pr1 = upk2(ar1);
            float2 pz0 = upk2(az0), pz1 = upk2(az1);
            float2 pn0 = upk2(an0), pn1 = upk2(an1);
            float* pp = &part[r * PPAD + kh * 4];
            pp[0] = (pr0.x + pr0.y) + (pr1.x + pr1.y);
            pp[1] = (pz0.x + pz0.y) + (pz1.x + pz1.y);
            pp[2] = (pn0.x + pn0.y) + (pn1.x + pn1.y);
            __syncthreads();

            if (tid < 128) {
                const float* pr = &part[r * PPAD];
                float hr = pr[0] + pr[4] + pr[8]  + pr[12] + bhr;
                float hz = pr[1] + pr[5] + pr[9]  + pr[13] + bhz;
                float hn = pr[2] + pr[6] + pr[10] + pr[14] + bhn;

                float rg = sigmoidf_(xr + hr);
                float zg = sigmoidf_(xz + hz);
                float ng = tanhf(xn + rg * hn);
                float h_new = (1.0f - zg) * ng + zg * hsm[b * HPAD + i];

                g_hs[((size_t)t * B_SZ + b) * H_SZ + i] = h_new;
                g_ah[((size_t)t * B_SZ + b) * H_SZ + i] = __float2half_rn(h_new);
            }

            // grid barrier over the 128 GRU CTAs (8 split counters)
            __syncthreads();
            if (tid == 0) {
                __threadfence();
                atomicAdd(&g_bars[(cta & (NBAR - 1)) * BARSTRIDE], 1u);
            }
            if (tid < 32) {
                const unsigned need = (unsigned)((NGRU / NBAR) * (t + 1));
                bool ok;
                do {
                    unsigned v = (tid < NBAR) ? ld_acq(&g_bars[tid * BARSTRIDE])
                                              : need;
                    ok = (v >= need);
                } while (__ballot_sync(0xffffffffu, ok) != 0xffffffffu);
            }
            // publish progress for the logits workers (single line)
            if (cta == 0 && tid == 0) st_rel(&g_tdone, (unsigned)(t + 1));
            __syncthreads();
        }
    }

    // ---------------- worker role (all CTAs) ----------------
    const uint32_t smb = smem_u32(fsm);
    __shared__ unsigned sjob[2];
    for (unsigned it = 0;; it++) {
        if (tid == 0) sjob[it & 1] = atomicAdd(&g_job, 1u);
        __syncthreads();
        unsigned j = sjob[it & 1];
        if (j >= (unsigned)NJOBS) break;
        int mb = (int)(j / NB_N);
        int nb = (int)(j % NB_N);
        // rows m0..m0+127 cover t in [mb*4, mb*4+3] -> need mb*4+4 steps done
        if (tid == 0) {
            unsigned need = (unsigned)(mb * 4 + 4);
            while (ld_acq(&g_tdone) < need) nsleep(128);
        }
        __syncthreads();
        logits_tile(mb * LMT, nb * LNT, smb, b_out, out);
        __syncthreads();
    }
}

// =====================================================================
// kernel_launch: convert -> embed_mma -> reset -> fused (4 launches)
// =====================================================================
extern "C" void kernel_launch(void* const* d_in, const int* in_sizes, int n_in,
                              void* d_out, int out_size)
{
    const float* emb    = (const float*)d_in[0];  // [V, H]
    const float* w_ih   = (const float*)d_in[1];  // [3H, H]
    const float* w_hh   = (const float*)d_in[2];  // [3H, H]
    const float* b_ih   = (const float*)d_in[3];  // [3H]
    const float* b_hh   = (const float*)d_in[4];  // [3H]
    const float* b_out  = (const float*)d_in[5];  // [V]
    const float* enc    = (const float*)d_in[6];  // [1, B, H]
    const int*   target = (const int*)d_in[7];    // [B, T]
    float* out = (float*)d_out;                   // [B, T, V]

    (void)in_sizes; (void)n_in; (void)out_size;

    static bool attr_done = false;
    if (!attr_done) {
        cudaFuncSetAttribute(embed_mma_kernel,
                             cudaFuncAttributeMaxDynamicSharedMemorySize, XTOT_B);
        cudaFuncSetAttribute(fused_kernel,
                             cudaFuncAttributeMaxDynamicSharedMemorySize,
                             FUSED_SMEM_BYTES);
        attr_done = true;
    }

    convert_kernel<<<CONV_GRID, 256>>>(emb, w_ih);

    embed_mma_kernel<<<dim3(M_ROWS / 128, G3 / 128), 256, XTOT_B>>>(b_ih, target);

    reset_bar_kernel<<<1, 32>>>();

    fused_kernel<<<NCTA_FUSED, 512, FUSED_SMEM_BYTES>>>(
        w_hh, b_hh, enc, b_out, out);
}